// round 8
// baseline (speedup 1.0000x reference)
#include <cuda_runtime.h>
#include <math.h>

#define BB 32
#define PP 8732
#define MM 16
#define CC 81
#define THRESH 0.5f
#define NBLK 16
#define CH ((PP + NBLK - 1) / NBLK)     // 546 priors per match chunk
#define MB (BB * NBLK)                  // 512 match blocks
#define LSEB ((BB * PP) / 128)          // 2183 lse blocks (exact: 279424/128)
#define NB2 8
#define CH2 ((PP + NB2 - 1) / NB2)      // 1092 priors per finalize chunk

typedef unsigned long long ull;

// Scratch (no allocation allowed -> __device__ globals)
__device__ ull   g_pfo_part[BB * MM * NBLK];  // per-object partial keys
__device__ ull   g_pbest[BB * PP];            // per-prior (iou<<32 | 15-obj)
__device__ float g_lse[BB * PP];              // per-prior logsumexp
__device__ float g_negloss[BB * PP];
__device__ int   g_npos[BB];
__device__ float g_locsum[BB];
__device__ float g_acc2[2];    // 0: pos_conf_sum, 1: hard_neg_sum
__device__ int   g_done;

// ==== K1: match blocks (one IoU pass, both reductions) + lse blocks ====
__global__ void __launch_bounds__(128, 10) k1_kernel(
        const float* __restrict__ logits,
        const float* __restrict__ boxes,
        const float* __restrict__ priors) {
    // small smem: only the match path uses it (~11.2KB)
    __shared__ float s_iou[CH][4];
    __shared__ unsigned char s_obj[CH][4];
    __shared__ float s_box[MM][4];
    __shared__ float s_area[MM];

    const int tid = threadIdx.x;

    if (blockIdx.x < MB) {
        // -------- match path: 4 warps x 4 objects over a 546-prior chunk ----
        const int b = blockIdx.x >> 4, c = blockIdx.x & 15;
        const int lane = tid & 31, warp = tid >> 5;

        if (tid == 0 && c == 0) {
            g_locsum[b] = 0.f; g_npos[b] = 0;
            if (b == 0) { g_acc2[0] = 0.f; g_acc2[1] = 0.f; g_done = 0; }
        }
        if (tid < MM) {
            float4 bx = ((const float4*)boxes)[b * MM + tid];
            s_box[tid][0] = bx.x; s_box[tid][1] = bx.y;
            s_box[tid][2] = bx.z; s_box[tid][3] = bx.w;
            s_area[tid] = (bx.z - bx.x) * (bx.w - bx.y);
        }
        __syncthreads();

        const int mb = warp * 4;   // this warp's 4 objects
        float ax[4], ay[4], az[4], aw[4], ar[4];
#pragma unroll
        for (int j = 0; j < 4; j++) {
            ax[j] = s_box[mb + j][0]; ay[j] = s_box[mb + j][1];
            az[j] = s_box[mb + j][2]; aw[j] = s_box[mb + j][3];
            ar[j] = s_area[mb + j];
        }

        const int p0 = c * CH;
        const int p1 = (p0 + CH < PP) ? p0 + CH : PP;

        float biou[4]; int bp[4];
#pragma unroll
        for (int j = 0; j < 4; j++) { biou[j] = -1.f; bp[j] = 0; }

        for (int p = p0 + lane; p < p1; p += 32) {   // ascending p per lane
            float4 pr = ((const float4*)priors)[p];
            float px0 = pr.x - pr.z * 0.5f, py0 = pr.y - pr.w * 0.5f;
            float px1 = pr.x + pr.z * 0.5f, py1 = pr.y + pr.w * 0.5f;
            float parea = pr.z * pr.w;

            float q[4];
#pragma unroll
            for (int j = 0; j < 4; j++) {
                float iw = fmaxf(fminf(az[j], px1) - fmaxf(ax[j], px0), 0.f);
                float ih = fmaxf(fminf(aw[j], py1) - fmaxf(ay[j], py0), 0.f);
                float inter = iw * ih;
                q[j] = inter / (ar[j] + parea - inter);
                if (q[j] > biou[j]) { biou[j] = q[j]; bp[j] = p; } // lowest p
            }
            // per-prior best of this warp's 4 objects (strict >: lowest j)
            float qb = q[0]; int jb = 0;
#pragma unroll
            for (int j = 1; j < 4; j++)
                if (q[j] > qb) { qb = q[j]; jb = j; }
            s_iou[p - p0][warp] = qb;
            s_obj[p - p0][warp] = (unsigned char)(mb + jb);
        }

        // per-object partial keys -> global
#pragma unroll
        for (int j = 0; j < 4; j++) {
            ull k = (biou[j] < 0.f) ? 0ull :
                ((((ull)__float_as_uint(biou[j])) << 32) |
                 (ull)(~(unsigned)bp[j]));
#pragma unroll
            for (int o = 16; o > 0; o >>= 1) {
                ull t = __shfl_down_sync(0xffffffffu, k, o);
                if (t > k) k = t;
            }
            if (lane == 0) g_pfo_part[(b * MM + mb + j) * NBLK + c] = k;
        }
        __syncthreads();

        // combine per-prior results across warps (ascending w: lowest m on ties)
        const int np = p1 - p0;
        for (int p = tid; p < np; p += 128) {
            float qb = s_iou[p][0]; int obj = s_obj[p][0];
#pragma unroll
            for (int w = 1; w < 4; w++) {
                float qw = s_iou[p][w];
                if (qw > qb) { qb = qw; obj = s_obj[p][w]; }
            }
            g_pbest[b * PP + p0 + p] =
                (((ull)__float_as_uint(qb)) << 32) | (unsigned)(15 - obj);
        }
    } else {
        // -------- lse path: thread-per-row, direct global loads, no smem ----
        const int r = (blockIdx.x - MB) * 128 + tid;   // exact grid, no guard
        const float* row = logits + (size_t)r * CC;
        float sum = 0.f;
#pragma unroll
        for (int i = 0; i < CC; i++) sum += __expf(row[i]);
        g_lse[r] = __logf(sum);
    }
}

// ==== K2: finalize per prior (no IoU recompute) ====
__global__ void __launch_bounds__(256) k2_kernel(
        const float* __restrict__ logits,
        const float* __restrict__ locs,
        const float* __restrict__ boxes,
        const int*   __restrict__ labels,
        const float* __restrict__ priors) {
    const int b = blockIdx.x >> 3, c = blockIdx.x & 7;
    const int tid = threadIdx.x;
    const int lane = tid & 31, warp = tid >> 5;

    __shared__ float s_box[MM][4];
    __shared__ int   s_lab[MM];
    __shared__ ull   s_part[MM * NBLK];   // 256
    __shared__ int   s_pfo[MM];
    __shared__ float s_wpos[8], s_wloc[8];
    __shared__ int   s_wcnt[8];

    s_part[tid] = g_pfo_part[b * (MM * NBLK) + tid];
    if (tid < MM) {
        float4 bx = ((const float4*)boxes)[b * MM + tid];
        s_box[tid][0] = bx.x; s_box[tid][1] = bx.y;
        s_box[tid][2] = bx.z; s_box[tid][3] = bx.w;
        s_lab[tid] = labels[b * MM + tid];
    }
    __syncthreads();
    if (tid < MM) {
        ull k = s_part[tid * NBLK];
#pragma unroll
        for (int i = 1; i < NBLK; i++)
            if (s_part[tid * NBLK + i] > k) k = s_part[tid * NBLK + i];
        s_pfo[tid] = (int)(~(unsigned)(k & 0xffffffffull));
    }
    __syncthreads();

    const int p0 = c * CH2;
    const int p1 = (p0 + CH2 < PP) ? p0 + CH2 : PP;

    float pos = 0.f, locsum = 0.f;
    int   posc = 0;
    for (int p = p0 + tid; p < p1; p += 256) {
        ull key = g_pbest[b * PP + p];
        float iou = __uint_as_float((unsigned)(key >> 32));
        int   obj = 15 - (int)(key & 0xffffffffull);
#pragma unroll
        for (int m = 0; m < MM; m++)         // forced: ascending m, last wins
            if (s_pfo[m] == p) { obj = m; iou = 1.0f; }

        const int lab = (iou < THRESH) ? 0 : s_lab[obj];
        float loss = g_lse[b * PP + p] - logits[((size_t)b * PP + p) * CC + lab];
        if (!isfinite(loss)) loss = 0.f;

        if (lab != 0) {
            pos += loss; posc++;
            g_negloss[b * PP + p] = 0.f;
            float4 pr = ((const float4*)priors)[p];
            float bx0 = s_box[obj][0], by0 = s_box[obj][1];
            float bx1 = s_box[obj][2], by1 = s_box[obj][3];
            float g0 = ((bx0 + bx1) * 0.5f - pr.x) * 10.f / pr.z;
            float g1 = ((by0 + by1) * 0.5f - pr.y) * 10.f / pr.w;
            float g2 = logf((bx1 - bx0) / pr.z) * 5.f;
            float g3 = logf((by1 - by0) / pr.w) * 5.f;
            float4 pl = ((const float4*)locs)[b * PP + p];
            locsum += fabsf(pl.x - g0) + fabsf(pl.y - g1)
                    + fabsf(pl.z - g2) + fabsf(pl.w - g3);
        } else {
            g_negloss[b * PP + p] = loss;
        }
    }

    for (int o = 16; o > 0; o >>= 1) {
        pos    += __shfl_xor_sync(0xffffffffu, pos, o);
        locsum += __shfl_xor_sync(0xffffffffu, locsum, o);
        posc   += __shfl_xor_sync(0xffffffffu, posc, o);
    }
    if (lane == 0) { s_wpos[warp] = pos; s_wloc[warp] = locsum; s_wcnt[warp] = posc; }
    __syncthreads();
    if (tid == 0) {
        float tp = 0.f, tl = 0.f; int tc = 0;
#pragma unroll
        for (int w = 0; w < 8; w++) { tp += s_wpos[w]; tl += s_wloc[w]; tc += s_wcnt[w]; }
        if (tp != 0.f) atomicAdd(&g_acc2[0], tp);
        if (tl != 0.f) atomicAdd(&g_locsum[b], tl);
        if (tc != 0)   atomicAdd(&g_npos[b], tc);
    }
}

// ==== K3: topk (exact, single-barrier iters, early exit) + final combine ====
#define NV ((PP + 255) / 256)   // 35
__global__ void __launch_bounds__(256) topk_kernel(float* __restrict__ out) {
    const int b = blockIdx.x, tid = threadIdx.x;
    const int lane = tid & 31, warp = tid >> 5;
    __shared__ int   s_cnt[2][8];
    __shared__ int   s_c2[8];
    __shared__ float s_sum[8];

    float v[NV];
#pragma unroll
    for (int i = 0; i < NV; i++) {
        int p = tid + i * 256;
        v[i] = (p < PP) ? g_negloss[b * PP + p] : -1.f;   // pad never counts
    }

    int K = g_npos[b] * 3;
    if (K > PP) K = PP;

    if (K > 0) {
        unsigned lo = 0u, hi = 0x7f7fffffu;
        int it = 0;
        while (lo < hi) {
            const unsigned mid = lo + ((hi - lo + 1u) >> 1);
            const float t = __uint_as_float(mid);
            int c = 0;
#pragma unroll
            for (int i = 0; i < NV; i++) c += (v[i] >= t) ? 1 : 0;
            c = __reduce_add_sync(0xffffffffu, c);
            const int par = it & 1;
            if (lane == 0) s_cnt[par][warp] = c;
            __syncthreads();
            int tot = 0;
#pragma unroll
            for (int w = 0; w < 8; w++) tot += s_cnt[par][w];
            if (tot == K) { lo = mid; break; }  // exact: top-K == {x >= mid}
            if (tot >= K) lo = mid; else hi = mid - 1u;
            it++;
        }
        const float thr = __uint_as_float(lo);

        int cgt = 0; float sgt = 0.f;
#pragma unroll
        for (int i = 0; i < NV; i++) {
            float x = v[i];
            if (x > thr) { cgt++; sgt += x; }
        }
        cgt = __reduce_add_sync(0xffffffffu, cgt);
        for (int o = 16; o > 0; o >>= 1)
            sgt += __shfl_xor_sync(0xffffffffu, sgt, o);
        if (lane == 0) { s_c2[warp] = cgt; s_sum[warp] = sgt; }
        __syncthreads();
        if (tid == 0) {
            int tc = 0; float ts = 0.f;
#pragma unroll
            for (int i = 0; i < 8; i++) { tc += s_c2[i]; ts += s_sum[i]; }
            atomicAdd(&g_acc2[1], ts + (float)(K - tc) * thr);
        }
    }

    __syncthreads();
    if (tid == 0) {
        __threadfence();
        int prev = atomicAdd(&g_done, 1);
        if (prev == BB - 1) {
            float n = 0.f, l = 0.f;
#pragma unroll
            for (int i = 0; i < BB; i++) { n += (float)g_npos[i]; l += g_locsum[i]; }
            out[0] = (g_acc2[0] + g_acc2[1]) / n + l / (4.f * n);
        }
    }
}

extern "C" void kernel_launch(void* const* d_in, const int* in_sizes, int n_in,
                              void* d_out, int out_size) {
    const float* locs   = (const float*)d_in[0];
    const float* logits = (const float*)d_in[1];
    const float* boxes  = (const float*)d_in[2];
    const int*   labels = (const int*)d_in[3];
    const float* priors = (const float*)d_in[4];
    float* out = (float*)d_out;

    k1_kernel<<<MB + LSEB, 128>>>(logits, boxes, priors);
    k2_kernel<<<BB * NB2, 256>>>(logits, locs, boxes, labels, priors);
    topk_kernel<<<BB, 256>>>(out);
}

// round 9
// speedup vs baseline: 1.2386x; 1.2386x over previous
#include <cuda_runtime.h>
#include <math.h>

#define BB 32
#define PP 8732
#define MM 16
#define CC 81
#define THRESH 0.5f
#define NBLK 16
#define CH ((PP + NBLK - 1) / NBLK)     // 546 priors per match chunk
#define MB (BB * NBLK)                  // 512 match blocks
#define ROWS_PER_BLK 32
#define LSEB ((BB * PP) / ROWS_PER_BLK) // 8732 lse blocks (exact)
#define NB2 8
#define CH2 ((PP + NB2 - 1) / NB2)      // 1092 priors per finalize chunk

typedef unsigned long long ull;

// Scratch (no allocation allowed -> __device__ globals)
__device__ ull   g_pfo_part[BB * MM * NBLK];  // per-object partial keys
__device__ ull   g_pbest[BB * PP];            // per-prior (iou<<32 | 15-obj)
__device__ float g_lse[BB * PP];              // per-prior logsumexp
__device__ float g_negloss[BB * PP];
__device__ int   g_npos[BB];
__device__ float g_locsum[BB];
__device__ float g_acc2[2];    // 0: pos_conf_sum, 1: hard_neg_sum
__device__ int   g_done;

// ==== K1: match blocks (one IoU pass, both reductions) + lse blocks ====
__global__ void __launch_bounds__(128) k1_kernel(
        const float* __restrict__ logits,
        const float* __restrict__ boxes,
        const float* __restrict__ priors) {
    // smem used only by the match path (~11.2KB; 512 of 9244 blocks)
    __shared__ float s_iou[CH][4];
    __shared__ unsigned char s_obj[CH][4];
    __shared__ float s_box[MM][4];
    __shared__ float s_area[MM];

    const int tid = threadIdx.x;
    const int lane = tid & 31, warp = tid >> 5;

    if (blockIdx.x >= MB) {
        // -------- lse path: warp-per-row, coalesced, no smem --------
        const int base = (blockIdx.x - MB) * ROWS_PER_BLK + warp * 8;
#pragma unroll
        for (int j = 0; j < 8; j++) {
            const int r = base + j;
            const float* rp = logits + (size_t)r * CC;
            float s = __expf(rp[lane]) + __expf(rp[lane + 32]);
            if (lane < 17) s += __expf(rp[lane + 64]);
#pragma unroll
            for (int o = 16; o > 0; o >>= 1)
                s += __shfl_xor_sync(0xffffffffu, s, o);
            if (lane == 0) g_lse[r] = __logf(s);
        }
        return;
    }

    // -------- match path: 4 warps x 4 objects over a 546-prior chunk ----
    const int b = blockIdx.x >> 4, c = blockIdx.x & 15;

    if (tid == 0 && c == 0) {
        g_locsum[b] = 0.f; g_npos[b] = 0;
        if (b == 0) { g_acc2[0] = 0.f; g_acc2[1] = 0.f; g_done = 0; }
    }
    if (tid < MM) {
        float4 bx = ((const float4*)boxes)[b * MM + tid];
        s_box[tid][0] = bx.x; s_box[tid][1] = bx.y;
        s_box[tid][2] = bx.z; s_box[tid][3] = bx.w;
        s_area[tid] = (bx.z - bx.x) * (bx.w - bx.y);
    }
    __syncthreads();

    const int mb = warp * 4;   // this warp's 4 objects
    float ax[4], ay[4], az[4], aw[4], ar[4];
#pragma unroll
    for (int j = 0; j < 4; j++) {
        ax[j] = s_box[mb + j][0]; ay[j] = s_box[mb + j][1];
        az[j] = s_box[mb + j][2]; aw[j] = s_box[mb + j][3];
        ar[j] = s_area[mb + j];
    }

    const int p0 = c * CH;
    const int p1 = (p0 + CH < PP) ? p0 + CH : PP;

    float biou[4]; int bp[4];
#pragma unroll
    for (int j = 0; j < 4; j++) { biou[j] = -1.f; bp[j] = 0; }

    for (int p = p0 + lane; p < p1; p += 32) {   // ascending p per lane
        float4 pr = ((const float4*)priors)[p];
        float px0 = pr.x - pr.z * 0.5f, py0 = pr.y - pr.w * 0.5f;
        float px1 = pr.x + pr.z * 0.5f, py1 = pr.y + pr.w * 0.5f;
        float parea = pr.z * pr.w;

        float q[4];
#pragma unroll
        for (int j = 0; j < 4; j++) {
            float iw = fmaxf(fminf(az[j], px1) - fmaxf(ax[j], px0), 0.f);
            float ih = fmaxf(fminf(aw[j], py1) - fmaxf(ay[j], py0), 0.f);
            float inter = iw * ih;
            q[j] = inter / (ar[j] + parea - inter);
            if (q[j] > biou[j]) { biou[j] = q[j]; bp[j] = p; } // lowest p
        }
        // per-prior best of this warp's 4 objects (strict >: lowest j)
        float qb = q[0]; int jb = 0;
#pragma unroll
        for (int j = 1; j < 4; j++)
            if (q[j] > qb) { qb = q[j]; jb = j; }
        s_iou[p - p0][warp] = qb;
        s_obj[p - p0][warp] = (unsigned char)(mb + jb);
    }

    // per-object partial keys -> global
#pragma unroll
    for (int j = 0; j < 4; j++) {
        ull k = (biou[j] < 0.f) ? 0ull :
            ((((ull)__float_as_uint(biou[j])) << 32) |
             (ull)(~(unsigned)bp[j]));
#pragma unroll
        for (int o = 16; o > 0; o >>= 1) {
            ull t = __shfl_down_sync(0xffffffffu, k, o);
            if (t > k) k = t;
        }
        if (lane == 0) g_pfo_part[(b * MM + mb + j) * NBLK + c] = k;
    }
    __syncthreads();

    // combine per-prior results across warps (ascending w: lowest m on ties)
    const int np = p1 - p0;
    for (int p = tid; p < np; p += 128) {
        float qb = s_iou[p][0]; int obj = s_obj[p][0];
#pragma unroll
        for (int w = 1; w < 4; w++) {
            float qw = s_iou[p][w];
            if (qw > qb) { qb = qw; obj = s_obj[p][w]; }
        }
        g_pbest[b * PP + p0 + p] =
            (((ull)__float_as_uint(qb)) << 32) | (unsigned)(15 - obj);
    }
}

// ==== K2: finalize per prior (no IoU recompute) ====
__global__ void __launch_bounds__(256) k2_kernel(
        const float* __restrict__ logits,
        const float* __restrict__ locs,
        const float* __restrict__ boxes,
        const int*   __restrict__ labels,
        const float* __restrict__ priors) {
    const int b = blockIdx.x >> 3, c = blockIdx.x & 7;
    const int tid = threadIdx.x;
    const int lane = tid & 31, warp = tid >> 5;

    __shared__ float s_box[MM][4];
    __shared__ int   s_lab[MM];
    __shared__ ull   s_part[MM * NBLK];   // 256
    __shared__ int   s_pfo[MM];
    __shared__ float s_wpos[8], s_wloc[8];
    __shared__ int   s_wcnt[8];

    s_part[tid] = g_pfo_part[b * (MM * NBLK) + tid];
    if (tid < MM) {
        float4 bx = ((const float4*)boxes)[b * MM + tid];
        s_box[tid][0] = bx.x; s_box[tid][1] = bx.y;
        s_box[tid][2] = bx.z; s_box[tid][3] = bx.w;
        s_lab[tid] = labels[b * MM + tid];
    }
    __syncthreads();
    if (tid < MM) {
        ull k = s_part[tid * NBLK];
#pragma unroll
        for (int i = 1; i < NBLK; i++)
            if (s_part[tid * NBLK + i] > k) k = s_part[tid * NBLK + i];
        s_pfo[tid] = (int)(~(unsigned)(k & 0xffffffffull));
    }
    __syncthreads();

    const int p0 = c * CH2;
    const int p1 = (p0 + CH2 < PP) ? p0 + CH2 : PP;

    float pos = 0.f, locsum = 0.f;
    int   posc = 0;
    for (int p = p0 + tid; p < p1; p += 256) {
        ull key = g_pbest[b * PP + p];
        float iou = __uint_as_float((unsigned)(key >> 32));
        int   obj = 15 - (int)(key & 0xffffffffull);
#pragma unroll
        for (int m = 0; m < MM; m++)         // forced: ascending m, last wins
            if (s_pfo[m] == p) { obj = m; iou = 1.0f; }

        const int lab = (iou < THRESH) ? 0 : s_lab[obj];
        float loss = g_lse[b * PP + p] - logits[((size_t)b * PP + p) * CC + lab];
        if (!isfinite(loss)) loss = 0.f;

        if (lab != 0) {
            pos += loss; posc++;
            g_negloss[b * PP + p] = 0.f;
            float4 pr = ((const float4*)priors)[p];
            float bx0 = s_box[obj][0], by0 = s_box[obj][1];
            float bx1 = s_box[obj][2], by1 = s_box[obj][3];
            float g0 = ((bx0 + bx1) * 0.5f - pr.x) * 10.f / pr.z;
            float g1 = ((by0 + by1) * 0.5f - pr.y) * 10.f / pr.w;
            float g2 = logf((bx1 - bx0) / pr.z) * 5.f;
            float g3 = logf((by1 - by0) / pr.w) * 5.f;
            float4 pl = ((const float4*)locs)[b * PP + p];
            locsum += fabsf(pl.x - g0) + fabsf(pl.y - g1)
                    + fabsf(pl.z - g2) + fabsf(pl.w - g3);
        } else {
            g_negloss[b * PP + p] = loss;
        }
    }

    for (int o = 16; o > 0; o >>= 1) {
        pos    += __shfl_xor_sync(0xffffffffu, pos, o);
        locsum += __shfl_xor_sync(0xffffffffu, locsum, o);
        posc   += __shfl_xor_sync(0xffffffffu, posc, o);
    }
    if (lane == 0) { s_wpos[warp] = pos; s_wloc[warp] = locsum; s_wcnt[warp] = posc; }
    __syncthreads();
    if (tid == 0) {
        float tp = 0.f, tl = 0.f; int tc = 0;
#pragma unroll
        for (int w = 0; w < 8; w++) { tp += s_wpos[w]; tl += s_wloc[w]; tc += s_wcnt[w]; }
        if (tp != 0.f) atomicAdd(&g_acc2[0], tp);
        if (tl != 0.f) atomicAdd(&g_locsum[b], tl);
        if (tc != 0)   atomicAdd(&g_npos[b], tc);
    }
}

// ==== K3: topk (exact, single-barrier iters, early exit) + final combine ====
#define NV ((PP + 255) / 256)   // 35
__global__ void __launch_bounds__(256) topk_kernel(float* __restrict__ out) {
    const int b = blockIdx.x, tid = threadIdx.x;
    const int lane = tid & 31, warp = tid >> 5;
    __shared__ int   s_cnt[2][8];
    __shared__ int   s_c2[8];
    __shared__ float s_sum[8];

    float v[NV];
#pragma unroll
    for (int i = 0; i < NV; i++) {
        int p = tid + i * 256;
        v[i] = (p < PP) ? g_negloss[b * PP + p] : -1.f;   // pad never counts
    }

    int K = g_npos[b] * 3;
    if (K > PP) K = PP;

    if (K > 0) {
        unsigned lo = 0u, hi = 0x7f7fffffu;
        int it = 0;
        while (lo < hi) {
            const unsigned mid = lo + ((hi - lo + 1u) >> 1);
            const float t = __uint_as_float(mid);
            int c = 0;
#pragma unroll
            for (int i = 0; i < NV; i++) c += (v[i] >= t) ? 1 : 0;
            c = __reduce_add_sync(0xffffffffu, c);
            const int par = it & 1;
            if (lane == 0) s_cnt[par][warp] = c;
            __syncthreads();
            int tot = 0;
#pragma unroll
            for (int w = 0; w < 8; w++) tot += s_cnt[par][w];
            if (tot == K) { lo = mid; break; }  // exact: top-K == {x >= mid}
            if (tot >= K) lo = mid; else hi = mid - 1u;
            it++;
        }
        const float thr = __uint_as_float(lo);

        int cgt = 0; float sgt = 0.f;
#pragma unroll
        for (int i = 0; i < NV; i++) {
            float x = v[i];
            if (x > thr) { cgt++; sgt += x; }
        }
        cgt = __reduce_add_sync(0xffffffffu, cgt);
        for (int o = 16; o > 0; o >>= 1)
            sgt += __shfl_xor_sync(0xffffffffu, sgt, o);
        if (lane == 0) { s_c2[warp] = cgt; s_sum[warp] = sgt; }
        __syncthreads();
        if (tid == 0) {
            int tc = 0; float ts = 0.f;
#pragma unroll
            for (int i = 0; i < 8; i++) { tc += s_c2[i]; ts += s_sum[i]; }
            atomicAdd(&g_acc2[1], ts + (float)(K - tc) * thr);
        }
    }

    __syncthreads();
    if (tid == 0) {
        __threadfence();
        int prev = atomicAdd(&g_done, 1);
        if (prev == BB - 1) {
            float n = 0.f, l = 0.f;
#pragma unroll
            for (int i = 0; i < BB; i++) { n += (float)g_npos[i]; l += g_locsum[i]; }
            out[0] = (g_acc2[0] + g_acc2[1]) / n + l / (4.f * n);
        }
    }
}

extern "C" void kernel_launch(void* const* d_in, const int* in_sizes, int n_in,
                              void* d_out, int out_size) {
    const float* locs   = (const float*)d_in[0];
    const float* logits = (const float*)d_in[1];
    const float* boxes  = (const float*)d_in[2];
    const int*   labels = (const int*)d_in[3];
    const float* priors = (const float*)d_in[4];
    float* out = (float*)d_out;

    k1_kernel<<<MB + LSEB, 128>>>(logits, boxes, priors);
    k2_kernel<<<BB * NB2, 256>>>(logits, locs, boxes, labels, priors);
    topk_kernel<<<BB, 256>>>(out);
}

// round 10
// speedup vs baseline: 1.2393x; 1.0006x over previous
#include <cuda_runtime.h>
#include <math.h>

#define BB 32
#define PP 8732
#define MM 16
#define CC 81
#define THRESH 0.5f
#define NBLK 16
#define CH ((PP + NBLK - 1) / NBLK)     // 546 priors per match chunk
#define MB (BB * NBLK)                  // 512 match blocks
#define ROWS_PER_BLK 16                 // 4 warps x 4 rows
#define LSEB ((BB * PP) / ROWS_PER_BLK) // 17464 lse blocks (exact)
#define NB2 8
#define CH2 ((PP + NB2 - 1) / NB2)      // 1092 priors per finalize chunk

typedef unsigned long long ull;

// Scratch (no allocation allowed -> __device__ globals)
__device__ ull   g_pfo_part[BB * MM * NBLK];  // per-object partial keys
__device__ ull   g_pbest[BB * PP];            // per-prior (iou<<32 | 15-obj)
__device__ float g_lse[BB * PP];              // per-prior logsumexp
__device__ float g_negloss[BB * PP];
__device__ int   g_npos[BB];
__device__ float g_locsum[BB];
__device__ float g_acc2[2];    // 0: pos_conf_sum, 1: hard_neg_sum
__device__ int   g_done;

// ==== K1: match blocks (one IoU pass, both reductions) + lse blocks ====
__global__ void __launch_bounds__(128) k1_kernel(
        const float* __restrict__ logits,
        const float* __restrict__ boxes,
        const float* __restrict__ priors) {
    // smem used only by the match path (~11.2KB; 512 of ~18K blocks)
    __shared__ float s_iou[CH][4];
    __shared__ unsigned char s_obj[CH][4];
    __shared__ float s_box[MM][4];
    __shared__ float s_area[MM];

    const int tid = threadIdx.x;
    const int lane = tid & 31, warp = tid >> 5;

    if (blockIdx.x >= MB) {
        // -------- lse path: 8-lane group per row, 4 rows/warp, no smem ----
        const int g = lane >> 3, k = lane & 7;
        const int r = ((blockIdx.x - MB) * 4 + warp) * 4 + g;
        const float* rp = logits + (size_t)r * CC + k;
        float s = 0.f;
#pragma unroll
        for (int i = 0; i < 10; i++) s += __expf(rp[i * 8]);
        if (k == 0) s += __expf(rp[80]);
        s += __shfl_xor_sync(0xffffffffu, s, 4);
        s += __shfl_xor_sync(0xffffffffu, s, 2);
        s += __shfl_xor_sync(0xffffffffu, s, 1);
        if (k == 0) g_lse[r] = __logf(s);
        return;
    }

    // -------- match path: 4 warps x 4 objects over a 546-prior chunk ----
    const int b = blockIdx.x >> 4, c = blockIdx.x & 15;

    if (tid == 0 && c == 0) {
        g_locsum[b] = 0.f; g_npos[b] = 0;
        if (b == 0) { g_acc2[0] = 0.f; g_acc2[1] = 0.f; g_done = 0; }
    }
    if (tid < MM) {
        float4 bx = ((const float4*)boxes)[b * MM + tid];
        s_box[tid][0] = bx.x; s_box[tid][1] = bx.y;
        s_box[tid][2] = bx.z; s_box[tid][3] = bx.w;
        s_area[tid] = (bx.z - bx.x) * (bx.w - bx.y);
    }
    __syncthreads();

    const int mb = warp * 4;   // this warp's 4 objects
    float ax[4], ay[4], az[4], aw[4], ar[4];
#pragma unroll
    for (int j = 0; j < 4; j++) {
        ax[j] = s_box[mb + j][0]; ay[j] = s_box[mb + j][1];
        az[j] = s_box[mb + j][2]; aw[j] = s_box[mb + j][3];
        ar[j] = s_area[mb + j];
    }

    const int p0 = c * CH;
    const int p1 = (p0 + CH < PP) ? p0 + CH : PP;

    float biou[4]; int bp[4];
#pragma unroll
    for (int j = 0; j < 4; j++) { biou[j] = -1.f; bp[j] = 0; }

    for (int p = p0 + lane; p < p1; p += 32) {   // ascending p per lane
        float4 pr = ((const float4*)priors)[p];
        float px0 = pr.x - pr.z * 0.5f, py0 = pr.y - pr.w * 0.5f;
        float px1 = pr.x + pr.z * 0.5f, py1 = pr.y + pr.w * 0.5f;
        float parea = pr.z * pr.w;

        float q[4];
#pragma unroll
        for (int j = 0; j < 4; j++) {
            float iw = fmaxf(fminf(az[j], px1) - fmaxf(ax[j], px0), 0.f);
            float ih = fmaxf(fminf(aw[j], py1) - fmaxf(ay[j], py0), 0.f);
            float inter = iw * ih;
            q[j] = inter / (ar[j] + parea - inter);
            if (q[j] > biou[j]) { biou[j] = q[j]; bp[j] = p; } // lowest p
        }
        // per-prior best of this warp's 4 objects (strict >: lowest j)
        float qb = q[0]; int jb = 0;
#pragma unroll
        for (int j = 1; j < 4; j++)
            if (q[j] > qb) { qb = q[j]; jb = j; }
        s_iou[p - p0][warp] = qb;
        s_obj[p - p0][warp] = (unsigned char)(mb + jb);
    }

    // per-object partial keys -> global
#pragma unroll
    for (int j = 0; j < 4; j++) {
        ull k = (biou[j] < 0.f) ? 0ull :
            ((((ull)__float_as_uint(biou[j])) << 32) |
             (ull)(~(unsigned)bp[j]));
#pragma unroll
        for (int o = 16; o > 0; o >>= 1) {
            ull t = __shfl_down_sync(0xffffffffu, k, o);
            if (t > k) k = t;
        }
        if (lane == 0) g_pfo_part[(b * MM + mb + j) * NBLK + c] = k;
    }
    __syncthreads();

    // combine per-prior results across warps (ascending w: lowest m on ties)
    const int np = p1 - p0;
    for (int p = tid; p < np; p += 128) {
        float qb = s_iou[p][0]; int obj = s_obj[p][0];
#pragma unroll
        for (int w = 1; w < 4; w++) {
            float qw = s_iou[p][w];
            if (qw > qb) { qb = qw; obj = s_obj[p][w]; }
        }
        g_pbest[b * PP + p0 + p] =
            (((ull)__float_as_uint(qb)) << 32) | (unsigned)(15 - obj);
    }
}

// ==== K2: finalize per prior (no IoU recompute) ====
__global__ void __launch_bounds__(256) k2_kernel(
        const float* __restrict__ logits,
        const float* __restrict__ locs,
        const float* __restrict__ boxes,
        const int*   __restrict__ labels,
        const float* __restrict__ priors) {
    const int b = blockIdx.x >> 3, c = blockIdx.x & 7;
    const int tid = threadIdx.x;
    const int lane = tid & 31, warp = tid >> 5;

    __shared__ float s_box[MM][4];
    __shared__ int   s_lab[MM];
    __shared__ ull   s_part[MM * NBLK];   // 256
    __shared__ int   s_pfo[MM];
    __shared__ float s_wpos[8], s_wloc[8];
    __shared__ int   s_wcnt[8];

    s_part[tid] = g_pfo_part[b * (MM * NBLK) + tid];
    if (tid < MM) {
        float4 bx = ((const float4*)boxes)[b * MM + tid];
        s_box[tid][0] = bx.x; s_box[tid][1] = bx.y;
        s_box[tid][2] = bx.z; s_box[tid][3] = bx.w;
        s_lab[tid] = labels[b * MM + tid];
    }
    __syncthreads();
    if (tid < MM) {
        ull k = s_part[tid * NBLK];
#pragma unroll
        for (int i = 1; i < NBLK; i++)
            if (s_part[tid * NBLK + i] > k) k = s_part[tid * NBLK + i];
        s_pfo[tid] = (int)(~(unsigned)(k & 0xffffffffull));
    }
    __syncthreads();

    const int p0 = c * CH2;
    const int p1 = (p0 + CH2 < PP) ? p0 + CH2 : PP;

    float pos = 0.f, locsum = 0.f;
    int   posc = 0;
    for (int p = p0 + tid; p < p1; p += 256) {
        ull key = g_pbest[b * PP + p];
        float iou = __uint_as_float((unsigned)(key >> 32));
        int   obj = 15 - (int)(key & 0xffffffffull);
#pragma unroll
        for (int m = 0; m < MM; m++)         // forced: ascending m, last wins
            if (s_pfo[m] == p) { obj = m; iou = 1.0f; }

        const int lab = (iou < THRESH) ? 0 : s_lab[obj];
        float loss = g_lse[b * PP + p] - logits[((size_t)b * PP + p) * CC + lab];
        if (!isfinite(loss)) loss = 0.f;

        if (lab != 0) {
            pos += loss; posc++;
            g_negloss[b * PP + p] = 0.f;
            float4 pr = ((const float4*)priors)[p];
            float bx0 = s_box[obj][0], by0 = s_box[obj][1];
            float bx1 = s_box[obj][2], by1 = s_box[obj][3];
            float g0 = ((bx0 + bx1) * 0.5f - pr.x) * 10.f / pr.z;
            float g1 = ((by0 + by1) * 0.5f - pr.y) * 10.f / pr.w;
            float g2 = logf((bx1 - bx0) / pr.z) * 5.f;
            float g3 = logf((by1 - by0) / pr.w) * 5.f;
            float4 pl = ((const float4*)locs)[b * PP + p];
            locsum += fabsf(pl.x - g0) + fabsf(pl.y - g1)
                    + fabsf(pl.z - g2) + fabsf(pl.w - g3);
        } else {
            g_negloss[b * PP + p] = loss;
        }
    }

    for (int o = 16; o > 0; o >>= 1) {
        pos    += __shfl_xor_sync(0xffffffffu, pos, o);
        locsum += __shfl_xor_sync(0xffffffffu, locsum, o);
        posc   += __shfl_xor_sync(0xffffffffu, posc, o);
    }
    if (lane == 0) { s_wpos[warp] = pos; s_wloc[warp] = locsum; s_wcnt[warp] = posc; }
    __syncthreads();
    if (tid == 0) {
        float tp = 0.f, tl = 0.f; int tc = 0;
#pragma unroll
        for (int w = 0; w < 8; w++) { tp += s_wpos[w]; tl += s_wloc[w]; tc += s_wcnt[w]; }
        if (tp != 0.f) atomicAdd(&g_acc2[0], tp);
        if (tl != 0.f) atomicAdd(&g_locsum[b], tl);
        if (tc != 0)   atomicAdd(&g_npos[b], tc);
    }
}

// ==== K3: topk (exact, single-barrier iters, early exit) + final combine ====
#define NV ((PP + 255) / 256)   // 35
__global__ void __launch_bounds__(256) topk_kernel(float* __restrict__ out) {
    const int b = blockIdx.x, tid = threadIdx.x;
    const int lane = tid & 31, warp = tid >> 5;
    __shared__ int   s_cnt[2][8];
    __shared__ int   s_c2[8];
    __shared__ float s_sum[8];

    float v[NV];
#pragma unroll
    for (int i = 0; i < NV; i++) {
        int p = tid + i * 256;
        v[i] = (p < PP) ? g_negloss[b * PP + p] : -1.f;   // pad never counts
    }

    int K = g_npos[b] * 3;
    if (K > PP) K = PP;

    if (K > 0) {
        unsigned lo = 0u, hi = 0x7f7fffffu;
        int it = 0;
        while (lo < hi) {
            const unsigned mid = lo + ((hi - lo + 1u) >> 1);
            const float t = __uint_as_float(mid);
            int c = 0;
#pragma unroll
            for (int i = 0; i < NV; i++) c += (v[i] >= t) ? 1 : 0;
            c = __reduce_add_sync(0xffffffffu, c);
            const int par = it & 1;
            if (lane == 0) s_cnt[par][warp] = c;
            __syncthreads();
            int tot = 0;
#pragma unroll
            for (int w = 0; w < 8; w++) tot += s_cnt[par][w];
            if (tot == K) { lo = mid; break; }  // exact: top-K == {x >= mid}
            if (tot >= K) lo = mid; else hi = mid - 1u;
            it++;
        }
        const float thr = __uint_as_float(lo);

        int cgt = 0; float sgt = 0.f;
#pragma unroll
        for (int i = 0; i < NV; i++) {
            float x = v[i];
            if (x > thr) { cgt++; sgt += x; }
        }
        cgt = __reduce_add_sync(0xffffffffu, cgt);
        for (int o = 16; o > 0; o >>= 1)
            sgt += __shfl_xor_sync(0xffffffffu, sgt, o);
        if (lane == 0) { s_c2[warp] = cgt; s_sum[warp] = sgt; }
        __syncthreads();
        if (tid == 0) {
            int tc = 0; float ts = 0.f;
#pragma unroll
            for (int i = 0; i < 8; i++) { tc += s_c2[i]; ts += s_sum[i]; }
            atomicAdd(&g_acc2[1], ts + (float)(K - tc) * thr);
        }
    }

    __syncthreads();
    if (tid == 0) {
        __threadfence();
        int prev = atomicAdd(&g_done, 1);
        if (prev == BB - 1) {
            float n = 0.f, l = 0.f;
#pragma unroll
            for (int i = 0; i < BB; i++) { n += (float)g_npos[i]; l += g_locsum[i]; }
            out[0] = (g_acc2[0] + g_acc2[1]) / n + l / (4.f * n);
        }
    }
}

extern "C" void kernel_launch(void* const* d_in, const int* in_sizes, int n_in,
                              void* d_out, int out_size) {
    const float* locs   = (const float*)d_in[0];
    const float* logits = (const float*)d_in[1];
    const float* boxes  = (const float*)d_in[2];
    const int*   labels = (const int*)d_in[3];
    const float* priors = (const float*)d_in[4];
    float* out = (float*)d_out;

    k1_kernel<<<MB + LSEB, 128>>>(logits, boxes, priors);
    k2_kernel<<<BB * NB2, 256>>>(logits, locs, boxes, labels, priors);
    topk_kernel<<<BB, 256>>>(out);
}